// round 4
// baseline (speedup 1.0000x reference)
#include <cuda_runtime.h>
#include <cuda_bf16.h>

// out[row, :] = W[days[row], :] + bias.  B*T = 131072 rows, D = 1024 fp32.
//
// Strategy: tile D into 8 chunks of 128 floats. Each CTA owns one chunk and
// stages the full 365-row W slice for that chunk (bias pre-added) in SMEM
// (365 * 512B = 186,880B). Inner loop per row is then:
//     day = days_s[r];  LDS.128 from slice;  STG.128 (512B/warp contiguous)
// This removes all per-element W reads from the L1TEX/L2 path (they were
// co-saturating with the store stream at ~80%), leaving L1TEX/L2/DRAM
// almost exclusively to the 537MB write stream.

static constexpr int D        = 1024;
static constexpr int D4       = D / 4;       // 256
static constexpr int CHUNK    = 128;         // floats per chunk
static constexpr int CHUNK4   = CHUNK / 4;   // 32 float4
static constexpr int NCHUNK   = D / CHUNK;   // 8
static constexpr int NDAYS    = 365;
static constexpr int THREADS  = 512;         // 16 warps
static constexpr int NGROUPS  = 128;         // row groups -> grid = 8*128 = 1024 CTAs

__global__ void __launch_bounds__(THREADS, 1)
doy_smem_slice_kernel(const int* __restrict__ days,
                      const float4* __restrict__ W4,
                      const float4* __restrict__ b4,
                      float4* __restrict__ out4,
                      int rows_per_group)
{
    extern __shared__ char smem_raw[];
    float4* slice4 = reinterpret_cast<float4*>(smem_raw);                    // [365][32] float4
    int*    days_s = reinterpret_cast<int*>(smem_raw + NDAYS * CHUNK * 4);  // [rows_per_group]

    const int tid   = threadIdx.x;
    const int chunk = blockIdx.x & (NCHUNK - 1);
    const int group = blockIdx.x >> 3;           // log2(NCHUNK)=3
    const int row0  = group * rows_per_group;
    const int cb4   = chunk * CHUNK4;            // float4 offset of chunk in a row

    // ---- Stage W slice (+bias) into SMEM ----
    {
        const int j4 = tid & (CHUNK4 - 1);       // 0..31 float4 column
        const int d0 = tid >> 5;                 // 0..15
        const float4 bv = __ldg(b4 + cb4 + j4);
        for (int d = d0; d < NDAYS; d += THREADS / CHUNK4) {
            float4 w = __ldg(W4 + (size_t)d * D4 + cb4 + j4);
            float4 v;
            v.x = w.x + bv.x;
            v.y = w.y + bv.y;
            v.z = w.z + bv.z;
            v.w = w.w + bv.w;
            slice4[d * CHUNK4 + j4] = v;
        }
    }
    // ---- Stage day indices ----
    for (int r = tid; r < rows_per_group; r += THREADS)
        days_s[r] = days[row0 + r];

    __syncthreads();

    // ---- Main loop: 16 warps, each warp writes one 512B row-chunk per step ----
    const int wid  = tid >> 5;
    const int lane = tid & 31;
    float4* outp = out4 + (size_t)row0 * D4 + cb4 + lane;

    int r = wid;
    const int nwarps = THREADS / 32;
    // unrolled by 4 for MLP on LDS + STG streams
    for (; r + 3 * nwarps < rows_per_group; r += 4 * nwarps) {
        int day0 = days_s[r];
        int day1 = days_s[r + nwarps];
        int day2 = days_s[r + 2 * nwarps];
        int day3 = days_s[r + 3 * nwarps];
        float4 v0 = slice4[day0 * CHUNK4 + lane];
        float4 v1 = slice4[day1 * CHUNK4 + lane];
        float4 v2 = slice4[day2 * CHUNK4 + lane];
        float4 v3 = slice4[day3 * CHUNK4 + lane];
        __stcs(outp + (size_t)r * D4, v0);
        __stcs(outp + (size_t)(r + nwarps) * D4, v1);
        __stcs(outp + (size_t)(r + 2 * nwarps) * D4, v2);
        __stcs(outp + (size_t)(r + 3 * nwarps) * D4, v3);
    }
    for (; r < rows_per_group; r += nwarps) {
        int day = days_s[r];
        __stcs(outp + (size_t)r * D4, slice4[day * CHUNK4 + lane]);
    }
}

extern "C" void kernel_launch(void* const* d_in, const int* in_sizes, int n_in,
                              void* d_out, int out_size)
{
    const int*    days = (const int*)d_in[0];
    const float4* W4   = (const float4*)d_in[1];
    const float4* b4   = (const float4*)d_in[2];
    float4*       out4 = (float4*)d_out;

    const int n_rows         = in_sizes[0];            // 131072
    const int rows_per_group = n_rows / NGROUPS;       // 1024

    const int smem_bytes = NDAYS * CHUNK * 4 + rows_per_group * 4;  // 186880 + 4096

    cudaFuncSetAttribute(doy_smem_slice_kernel,
                         cudaFuncAttributeMaxDynamicSharedMemorySize, smem_bytes);

    doy_smem_slice_kernel<<<NCHUNK * NGROUPS, THREADS, smem_bytes>>>(
        days, W4, b4, out4, rows_per_group);
}